// round 4
// baseline (speedup 1.0000x reference)
#include <cuda_runtime.h>
#include <cstdint>

// Problem constants
#define BB 16
#define NN 12800
#define FM 128          // F_MSG
#define FN 256          // F_NODE
#define NBINS 100       // N / BIN_SIZE
#define HB 50           // NBINS / 2
#define BS 128          // BIN_SIZE
#define NKEYS 200       // bin keys in [0, 198]
#define ROTC 100        // rot second-dim stride (MAX_NUM_BINS/2)

// Output layout (flattened float32, reference tuple order)
#define OFF_BINS   0
#define LEN_BINS   (BB * NN)                  // 204800
#define OFF_XNODE  (OFF_BINS + LEN_BINS)      // 204800
#define LEN_XNODE  (BB * NN * FN)             // 52428800
#define OFF_DM     (OFF_XNODE + LEN_XNODE)    // 52633600
#define LEN_DM     (BB * NN * BS)             // 26214400
#define OFF_MSKF   (OFF_DM + LEN_DM)          // 78848000

// Scratch (device globals: no allocation allowed)
__device__ int g_key[BB * NN];    // bin key per (b,n)
__device__ int g_bins[BB * NN];   // sorted original indices (bins_split)

typedef unsigned long long u64;

__device__ __forceinline__ float ex2f(float x) {
    float y; asm("ex2.approx.f32 %0, %1;" : "=f"(y) : "f"(x)); return y;
}
__device__ __forceinline__ float rsqf(float x) {
    float y; asm("rsqrt.approx.f32 %0, %1;" : "=f"(y) : "f"(x)); return y;
}
// packed fp32x2 helpers (bit-exact per-lane IEEE fp32 FMA)
__device__ __forceinline__ u64 pack2(float x, float y) {
    u64 r; asm("mov.b64 %0, {%1, %2};" : "=l"(r) : "f"(x), "f"(y)); return r;
}
__device__ __forceinline__ void unpack2(u64 v, float& x, float& y) {
    asm("mov.b64 {%0, %1}, %2;" : "=f"(x), "=f"(y) : "l"(v));
}
__device__ __forceinline__ void fma2(u64& d, u64 a, u64 b) {
    asm("fma.rn.f32x2 %0, %1, %2, %0;" : "+l"(d) : "l"(a), "l"(b));
}

// ---------------------------------------------------------------------------
// K1: LSH projection + argmax -> bin key.  Register-tiled GEMM.
// 128 threads per block, block = 128 nodes x 64 h (h 50..63 zero-padded;
// pads can never win either argmax branch). Thread tile = 8 nodes x 8 h.
// A-fragments straight from gmem (L1, each chunk read once/block);
// B-fragments from Rs smem, permuted so each LDS.128 is conflict-free.
// Rs physical layout per f-row (64 floats): phys = (e>>2)*32 + g*4 + (e&3)
// for h = g*8+e  ->  q0 = row[jx*4..+3] (e=0..3), q1 = row[32+jx*4..] (e=4..7).
// ---------------------------------------------------------------------------
__global__ void __launch_bounds__(128, 4)
k_proj(const float* __restrict__ x_msg,
       const int* __restrict__ msk,
       const float* __restrict__ rot) {
    const int b  = blockIdx.x / (NN / 128);
    const int n0 = (blockIdx.x % (NN / 128)) * 128;
    __shared__ float Rs[128 * 64];
    const int tid = threadIdx.x;
    const int jx = tid & 7;        // h-group 0..7
    const int iy = tid >> 3;       // node-group 0..15

    // stage Rs (rot is tiny & L2-resident; scattered reads OK)
    for (int idx = tid; idx < 128 * 64; idx += 128) {
        int f = idx >> 6, hp = idx & 63;
        int half = hp >> 5;               // e>>2
        int g    = (hp & 31) >> 2;
        int e    = (hp & 3) + half * 4;
        int h    = g * 8 + e;
        Rs[idx] = (h < HB) ? rot[f * ROTC + h] : 0.f;
    }
    __syncthreads();

    u64 acc[8][4];
#pragma unroll
    for (int k = 0; k < 8; k++)
#pragma unroll
        for (int p = 0; p < 4; p++) acc[k][p] = pack2(0.f, 0.f);

    const float4* xb4 = (const float4*)(x_msg + ((size_t)b * NN + n0) * FM);
    for (int f4 = 0; f4 < FM / 4; f4++) {
        float4 av[8];
#pragma unroll
        for (int k = 0; k < 8; k++)
            av[k] = xb4[(size_t)(iy * 8 + k) * (FM / 4) + f4];
#pragma unroll
        for (int ff = 0; ff < 4; ff++) {
            const float* rrow = Rs + (f4 * 4 + ff) * 64;
            ulonglong2 q0 = *(const ulonglong2*)(rrow + jx * 4);
            ulonglong2 q1 = *(const ulonglong2*)(rrow + 32 + jx * 4);
#pragma unroll
            for (int k = 0; k < 8; k++) {
                float a = (ff == 0) ? av[k].x : (ff == 1) ? av[k].y
                         : (ff == 2) ? av[k].z : av[k].w;
                u64 a2 = pack2(a, a);
                fma2(acc[k][0], a2, q0.x);
                fma2(acc[k][1], a2, q0.y);
                fma2(acc[k][2], a2, q1.x);
                fma2(acc[k][3], a2, q1.y);
            }
        }
    }

    // per-node argmax/argmin over 64 h (8 local + shuffle over 8 jx lanes)
#pragma unroll
    for (int k = 0; k < 8; k++) {
        float v[8];
#pragma unroll
        for (int p = 0; p < 4; p++) unpack2(acc[k][p], v[2 * p], v[2 * p + 1]);
        float bv = v[0]; int bh = jx * 8;
        float mv = v[0]; int mh = jx * 8;
#pragma unroll
        for (int e = 1; e < 8; e++) {
            int h = jx * 8 + e;
            if (v[e] > bv) { bv = v[e]; bh = h; }
            if (v[e] < mv) { mv = v[e]; mh = h; }
        }
#pragma unroll
        for (int off = 1; off < 8; off <<= 1) {
            float obv = __shfl_xor_sync(0xffffffffu, bv, off);
            int   obh = __shfl_xor_sync(0xffffffffu, bh, off);
            float omv = __shfl_xor_sync(0xffffffffu, mv, off);
            int   omh = __shfl_xor_sync(0xffffffffu, mh, off);
            if (obv > bv || (obv == bv && obh < bh)) { bv = obv; bh = obh; }
            if (omv < mv || (omv == mv && omh < mh)) { mv = omv; mh = omh; }
        }
        if (jx == 0) {
            int idx = (bv >= -mv) ? bh : (HB + mh);
            int n = n0 + iy * 8 + k;
            int m = msk[(size_t)b * NN + n];
            g_key[(size_t)b * NN + n] = idx + (m ? 0 : (NBINS - 1));
        }
    }
}

// ---------------------------------------------------------------------------
// K2: stable counting sort per batch (matches stable jnp.argsort).
// ---------------------------------------------------------------------------
__global__ void k_sort(const int* __restrict__ msk,
                       float* __restrict__ out) {
    const int b = blockIdx.x;
    extern __shared__ unsigned short off[];        // [NKEYS][128]
    __shared__ unsigned int keyTotal[NKEYS];
    __shared__ unsigned int keyBase[NKEYS];
    const int t = threadIdx.x;                     // 128 threads

    for (int i = t; i < NKEYS * 128; i += 128) off[i] = 0;
    __syncthreads();

    const int* kb = g_key + (size_t)b * NN;
    const int base_n = t * 100;
    for (int q = 0; q < 100; q++) {
        int k = kb[base_n + q];
        off[k * 128 + t]++;
    }
    __syncthreads();

    for (int k = t; k < NKEYS; k += 128) {
        unsigned int run = 0;
        for (int tt = 0; tt < 128; tt++) {
            unsigned short c = off[k * 128 + tt];
            off[k * 128 + tt] = (unsigned short)run;
            run += c;
        }
        keyTotal[k] = run;
    }
    __syncthreads();
    if (t == 0) {
        unsigned int run = 0;
        for (int k = 0; k < NKEYS; k++) { keyBase[k] = run; run += keyTotal[k]; }
    }
    __syncthreads();

    int* gb = g_bins + (size_t)b * NN;
    const int* mb = msk + (size_t)b * NN;
    float* out_bins = out + OFF_BINS + (size_t)b * NN;
    float* out_mskf = out + OFF_MSKF + (size_t)b * NN;
    for (int q = 0; q < 100; q++) {
        int n = base_n + q;
        int k = kb[n];
        unsigned int pos = keyBase[k] + off[k * 128 + t];
        off[k * 128 + t]++;
        gb[pos] = n;
        out_bins[pos] = (float)n;
        out_mskf[pos] = mb[n] ? 1.0f : 0.0f;
    }
}

// ---------------------------------------------------------------------------
// K4: per-bin pairwise gaussian kernel + fused x_node gather.
// ---------------------------------------------------------------------------
#define ST 132
__global__ void __launch_bounds__(256, 3)
k_dm(const float4* __restrict__ x_msg4,
     const int* __restrict__ msk,
     const float4* __restrict__ x_node4,
     float* __restrict__ out) {
    const int b   = blockIdx.x / NBINS;
    const int bin = blockIdx.x % NBINS;
    extern __shared__ float sm4[];
    float* As = sm4;                 // [128][ST], f-major (A transposed)
    float* na = sm4 + 128 * ST;      // [128]
    float* mm = na + 128;            // [128]
    const int tid  = threadIdx.x;    // 256
    const int w    = tid >> 5;
    const int lane = tid & 31;

    const int* gb = g_bins + ((size_t)b * NBINS + bin) * BS;
    const float4* xb = x_msg4 + (size_t)b * NN * (FM / 4);
    for (int r = w; r < BS; r += 8) {
        int src = gb[r];
        float m = msk[(size_t)b * NN + src] ? 1.f : 0.f;
        float4 v = xb[(size_t)src * (FM / 4) + lane];
        v.x *= m; v.y *= m; v.z *= m; v.w *= m;
        As[(4 * lane + 0) * ST + r] = v.x;
        As[(4 * lane + 1) * ST + r] = v.y;
        As[(4 * lane + 2) * ST + r] = v.z;
        As[(4 * lane + 3) * ST + r] = v.w;
        float s = v.x * v.x + v.y * v.y + v.z * v.z + v.w * v.w;
#pragma unroll
        for (int o = 16; o; o >>= 1) s += __shfl_xor_sync(0xffffffffu, s, o);
        if (lane == 0) { na[r] = s; mm[r] = m; }
    }
    __syncthreads();

    const int tx = tid & 15, ty = tid >> 4;
    const int i0 = ty * 8, j0 = tx * 8;
    u64 acc2[8][4];
#pragma unroll
    for (int u = 0; u < 8; u++)
#pragma unroll
        for (int v = 0; v < 4; v++) acc2[u][v] = pack2(0.f, 0.f);

    for (int f = 0; f < FM; f++) {
        const float* row = As + f * ST;
        float4 a0 = *(const float4*)(row + i0);
        float4 a1 = *(const float4*)(row + i0 + 4);
        ulonglong2 q0 = *(const ulonglong2*)(row + j0);
        ulonglong2 q1 = *(const ulonglong2*)(row + j0 + 4);
        float a[8] = {a0.x, a0.y, a0.z, a0.w, a1.x, a1.y, a1.z, a1.w};
        u64 bq[4] = {q0.x, q0.y, q1.x, q1.y};
#pragma unroll
        for (int u = 0; u < 8; u++) {
            u64 au = pack2(a[u], a[u]);
#pragma unroll
            for (int v = 0; v < 4; v++) fma2(acc2[u][v], au, bq[v]);
        }
    }

    float nai[8], mi[8], naj[8], mj[8];
#pragma unroll
    for (int u = 0; u < 8; u++) { nai[u] = na[i0 + u]; mi[u] = mm[i0 + u]; }
#pragma unroll
    for (int v = 0; v < 8; v++) { naj[v] = na[j0 + v]; mj[v] = mm[j0 + v]; }

    float* dout = out + OFF_DM + (size_t)blockIdx.x * BS * BS;
    const float c = -0.14426950408889634f;   // -DIST_MULT * log2(e)
#pragma unroll
    for (int u = 0; u < 8; u++) {
        float g[8];
#pragma unroll
        for (int v = 0; v < 4; v++) unpack2(acc2[u][v], g[2 * v], g[2 * v + 1]);
        float res[8];
#pragma unroll
        for (int v = 0; v < 8; v++) {
            float x = fmaxf(nai[u] + naj[v] - 2.0f * g[v], 1e-6f);
            float d = x * rsqf(x);            // sqrt(x), x >= 1e-6
            float val = ex2f(c * d) * mi[u] * mj[v];
            res[v] = fminf(val, 1.0f);
        }
        float4* p = (float4*)(dout + (i0 + u) * BS + j0);
        p[0] = make_float4(res[0], res[1], res[2], res[3]);
        p[1] = make_float4(res[4], res[5], res[6], res[7]);
    }

    // Fused x_node gather: this bin's 128 rows of 256 floats (64 float4).
    const float4* xn = x_node4 + (size_t)b * NN * (FN / 4);
    float4* xo = (float4*)(out + OFF_XNODE) + (size_t)blockIdx.x * BS * (FN / 4);
    for (int r = w; r < BS; r += 8) {
        int src = gb[r];
        const float4* s = xn + (size_t)src * (FN / 4);
        float4* d = xo + (size_t)r * (FN / 4);
#pragma unroll
        for (int c4 = 0; c4 < 2; c4++) d[lane + 32 * c4] = s[lane + 32 * c4];
    }
}

// ---------------------------------------------------------------------------
extern "C" void kernel_launch(void* const* d_in, const int* in_sizes, int n_in,
                              void* d_out, int out_size) {
    const float* x_msg  = (const float*)d_in[0];
    const float* x_node = (const float*)d_in[1];
    const int*   msk    = (const int*)d_in[2];
    const float* rot    = (const float*)d_in[3];
    float* out = (float*)d_out;

    const int SM2 = NKEYS * 128 * 2;                // 51200
    const int SM4 = 128 * ST * 4 + 2 * 128 * 4;     // 68608
    cudaFuncSetAttribute(k_sort, cudaFuncAttributeMaxDynamicSharedMemorySize, SM2);
    cudaFuncSetAttribute(k_dm,   cudaFuncAttributeMaxDynamicSharedMemorySize, SM4);

    k_proj<<<BB * (NN / 128), 128>>>(x_msg, msk, rot);
    k_sort<<<BB, 128, SM2>>>(msk, out);
    k_dm<<<BB * NBINS, 256, SM4>>>((const float4*)x_msg, msk,
                                   (const float4*)x_node, out);
}

// round 5
// speedup vs baseline: 1.6947x; 1.6947x over previous
#include <cuda_runtime.h>
#include <cstdint>

// Problem constants
#define BB 16
#define NN 12800
#define FM 128          // F_MSG
#define FN 256          // F_NODE
#define NBINS 100       // N / BIN_SIZE
#define HB 50           // NBINS / 2
#define BS 128          // BIN_SIZE
#define NKEYS 200      // bin keys in [0, 198]
#define ROTC 100        // rot second-dim stride (MAX_NUM_BINS/2)

// Output layout (flattened float32, reference tuple order)
#define OFF_BINS   0
#define LEN_BINS   (BB * NN)                  // 204800
#define OFF_XNODE  (OFF_BINS + LEN_BINS)      // 204800
#define LEN_XNODE  (BB * NN * FN)             // 52428800
#define OFF_DM     (OFF_XNODE + LEN_XNODE)    // 52633600
#define LEN_DM     (BB * NN * BS)             // 26214400
#define OFF_MSKF   (OFF_DM + LEN_DM)          // 78848000

// Scratch (device globals: no allocation allowed)
__device__ int g_key[BB * NN];    // bin key per (b,n)
__device__ int g_bins[BB * NN];   // sorted original indices (bins_split)

typedef unsigned long long u64;

__device__ __forceinline__ float ex2f(float x) {
    float y; asm("ex2.approx.f32 %0, %1;" : "=f"(y) : "f"(x)); return y;
}
__device__ __forceinline__ float rsqf(float x) {
    float y; asm("rsqrt.approx.f32 %0, %1;" : "=f"(y) : "f"(x)); return y;
}
// packed fp32x2 helpers (bit-exact per-lane IEEE fp32 FMA)
__device__ __forceinline__ u64 pack2(float x, float y) {
    u64 r; asm("mov.b64 %0, {%1, %2};" : "=l"(r) : "f"(x), "f"(y)); return r;
}
__device__ __forceinline__ void unpack2(u64 v, float& x, float& y) {
    asm("mov.b64 {%0, %1}, %2;" : "=f"(x), "=f"(y) : "l"(v));
}
__device__ __forceinline__ void fma2(u64& d, u64 a, u64 b) {
    asm("fma.rn.f32x2 %0, %1, %2, %0;" : "+l"(d) : "l"(a), "l"(b));
}

// ---------------------------------------------------------------------------
// K1: LSH projection + argmax -> bin key.  Register-tiled GEMM.
// 128 threads per block, block = 128 nodes x 64 h (h 50..63 zero-padded;
// pads can never win either argmax branch). Thread tile = 8 nodes x 8 h.
// ---------------------------------------------------------------------------
__global__ void __launch_bounds__(128, 4)
k_proj(const float* __restrict__ x_msg,
       const int* __restrict__ msk,
       const float* __restrict__ rot) {
    const int b  = blockIdx.x / (NN / 128);
    const int n0 = (blockIdx.x % (NN / 128)) * 128;
    __shared__ float Rs[128 * 64];
    const int tid = threadIdx.x;
    const int jx = tid & 7;        // h-group 0..7
    const int iy = tid >> 3;       // node-group 0..15

    // stage Rs (rot is tiny & L2-resident; scattered reads OK)
    for (int idx = tid; idx < 128 * 64; idx += 128) {
        int f = idx >> 6, hp = idx & 63;
        int half = hp >> 5;               // e>>2
        int g    = (hp & 31) >> 2;
        int e    = (hp & 3) + half * 4;
        int h    = g * 8 + e;
        Rs[idx] = (h < HB) ? rot[f * ROTC + h] : 0.f;
    }
    __syncthreads();

    u64 acc[8][4];
#pragma unroll
    for (int k = 0; k < 8; k++)
#pragma unroll
        for (int p = 0; p < 4; p++) acc[k][p] = pack2(0.f, 0.f);

    const float4* xb4 = (const float4*)(x_msg + ((size_t)b * NN + n0) * FM);
    for (int f4 = 0; f4 < FM / 4; f4++) {
        float4 av[8];
#pragma unroll
        for (int k = 0; k < 8; k++)
            av[k] = xb4[(size_t)(iy * 8 + k) * (FM / 4) + f4];
#pragma unroll
        for (int ff = 0; ff < 4; ff++) {
            const float* rrow = Rs + (f4 * 4 + ff) * 64;
            ulonglong2 q0 = *(const ulonglong2*)(rrow + jx * 4);
            ulonglong2 q1 = *(const ulonglong2*)(rrow + 32 + jx * 4);
#pragma unroll
            for (int k = 0; k < 8; k++) {
                float a = (ff == 0) ? av[k].x : (ff == 1) ? av[k].y
                         : (ff == 2) ? av[k].z : av[k].w;
                u64 a2 = pack2(a, a);
                fma2(acc[k][0], a2, q0.x);
                fma2(acc[k][1], a2, q0.y);
                fma2(acc[k][2], a2, q1.x);
                fma2(acc[k][3], a2, q1.y);
            }
        }
    }

    // per-node argmax/argmin over 64 h (8 local + shuffle over 8 jx lanes)
#pragma unroll
    for (int k = 0; k < 8; k++) {
        float v[8];
#pragma unroll
        for (int p = 0; p < 4; p++) unpack2(acc[k][p], v[2 * p], v[2 * p + 1]);
        float bv = v[0]; int bh = jx * 8;
        float mv = v[0]; int mh = jx * 8;
#pragma unroll
        for (int e = 1; e < 8; e++) {
            int h = jx * 8 + e;
            if (v[e] > bv) { bv = v[e]; bh = h; }
            if (v[e] < mv) { mv = v[e]; mh = h; }
        }
#pragma unroll
        for (int off = 1; off < 8; off <<= 1) {
            float obv = __shfl_xor_sync(0xffffffffu, bv, off);
            int   obh = __shfl_xor_sync(0xffffffffu, bh, off);
            float omv = __shfl_xor_sync(0xffffffffu, mv, off);
            int   omh = __shfl_xor_sync(0xffffffffu, mh, off);
            if (obv > bv || (obv == bv && obh < bh)) { bv = obv; bh = obh; }
            if (omv < mv || (omv == mv && omh < mh)) { mv = omv; mh = omh; }
        }
        if (jx == 0) {
            int idx = (bv >= -mv) ? bh : (HB + mh);
            int n = n0 + iy * 8 + k;
            int m = msk[(size_t)b * NN + n];
            g_key[(size_t)b * NN + n] = idx + (m ? 0 : (NBINS - 1));
        }
    }
}

// ---------------------------------------------------------------------------
// K2: stable counting sort per batch (matches stable jnp.argsort).
// ---------------------------------------------------------------------------
__global__ void k_sort(const int* __restrict__ msk,
                       float* __restrict__ out) {
    const int b = blockIdx.x;
    extern __shared__ unsigned short off[];        // [NKEYS][128]
    __shared__ unsigned int keyTotal[NKEYS];
    __shared__ unsigned int keyBase[NKEYS];
    const int t = threadIdx.x;                     // 128 threads

    for (int i = t; i < NKEYS * 128; i += 128) off[i] = 0;
    __syncthreads();

    const int* kb = g_key + (size_t)b * NN;
    const int base_n = t * 100;
    for (int q = 0; q < 100; q++) {
        int k = kb[base_n + q];
        off[k * 128 + t]++;
    }
    __syncthreads();

    for (int k = t; k < NKEYS; k += 128) {
        unsigned int run = 0;
        for (int tt = 0; tt < 128; tt++) {
            unsigned short c = off[k * 128 + tt];
            off[k * 128 + tt] = (unsigned short)run;
            run += c;
        }
        keyTotal[k] = run;
    }
    __syncthreads();
    if (t == 0) {
        unsigned int run = 0;
        for (int k = 0; k < NKEYS; k++) { keyBase[k] = run; run += keyTotal[k]; }
    }
    __syncthreads();

    int* gb = g_bins + (size_t)b * NN;
    const int* mb = msk + (size_t)b * NN;
    float* out_bins = out + OFF_BINS + (size_t)b * NN;
    float* out_mskf = out + OFF_MSKF + (size_t)b * NN;
    for (int q = 0; q < 100; q++) {
        int n = base_n + q;
        int k = kb[n];
        unsigned int pos = keyBase[k] + off[k * 128 + t];
        off[k * 128 + t]++;
        gb[pos] = n;
        out_bins[pos] = (float)n;
        out_mskf[pos] = mb[n] ? 1.0f : 0.0f;
    }
}

// ---------------------------------------------------------------------------
// K4: per-bin pairwise gaussian kernel + fused x_node gather.
// occ=2 (NOT 3: regs=94 needed; capping to 84 spills accumulators -> R4 regression)
// ---------------------------------------------------------------------------
#define ST 132
__global__ void __launch_bounds__(256, 2)
k_dm(const float4* __restrict__ x_msg4,
     const int* __restrict__ msk,
     const float4* __restrict__ x_node4,
     float* __restrict__ out) {
    const int b   = blockIdx.x / NBINS;
    const int bin = blockIdx.x % NBINS;
    extern __shared__ float sm4[];
    float* As = sm4;                 // [128][ST], f-major (A transposed)
    float* na = sm4 + 128 * ST;      // [128]
    float* mm = na + 128;            // [128]
    const int tid  = threadIdx.x;    // 256
    const int w    = tid >> 5;
    const int lane = tid & 31;

    const int* gb = g_bins + ((size_t)b * NBINS + bin) * BS;
    const float4* xb = x_msg4 + (size_t)b * NN * (FM / 4);
    for (int r = w; r < BS; r += 8) {
        int src = gb[r];
        float m = msk[(size_t)b * NN + src] ? 1.f : 0.f;
        float4 v = xb[(size_t)src * (FM / 4) + lane];
        v.x *= m; v.y *= m; v.z *= m; v.w *= m;
        As[(4 * lane + 0) * ST + r] = v.x;
        As[(4 * lane + 1) * ST + r] = v.y;
        As[(4 * lane + 2) * ST + r] = v.z;
        As[(4 * lane + 3) * ST + r] = v.w;
        float s = v.x * v.x + v.y * v.y + v.z * v.z + v.w * v.w;
#pragma unroll
        for (int o = 16; o; o >>= 1) s += __shfl_xor_sync(0xffffffffu, s, o);
        if (lane == 0) { na[r] = s; mm[r] = m; }
    }
    __syncthreads();

    const int tx = tid & 15, ty = tid >> 4;
    const int i0 = ty * 8, j0 = tx * 8;
    u64 acc2[8][4];
#pragma unroll
    for (int u = 0; u < 8; u++)
#pragma unroll
        for (int v = 0; v < 4; v++) acc2[u][v] = pack2(0.f, 0.f);

    for (int f = 0; f < FM; f++) {
        const float* row = As + f * ST;
        float4 a0 = *(const float4*)(row + i0);
        float4 a1 = *(const float4*)(row + i0 + 4);
        ulonglong2 q0 = *(const ulonglong2*)(row + j0);
        ulonglong2 q1 = *(const ulonglong2*)(row + j0 + 4);
        float a[8] = {a0.x, a0.y, a0.z, a0.w, a1.x, a1.y, a1.z, a1.w};
        u64 bq[4] = {q0.x, q0.y, q1.x, q1.y};
#pragma unroll
        for (int u = 0; u < 8; u++) {
            u64 au = pack2(a[u], a[u]);
#pragma unroll
            for (int v = 0; v < 4; v++) fma2(acc2[u][v], au, bq[v]);
        }
    }

    float nai[8], mi[8], naj[8], mj[8];
#pragma unroll
    for (int u = 0; u < 8; u++) { nai[u] = na[i0 + u]; mi[u] = mm[i0 + u]; }
#pragma unroll
    for (int v = 0; v < 8; v++) { naj[v] = na[j0 + v]; mj[v] = mm[j0 + v]; }

    float* dout = out + OFF_DM + (size_t)blockIdx.x * BS * BS;
    const float c = -0.14426950408889634f;   // -DIST_MULT * log2(e)
#pragma unroll
    for (int u = 0; u < 8; u++) {
        float g[8];
#pragma unroll
        for (int v = 0; v < 4; v++) unpack2(acc2[u][v], g[2 * v], g[2 * v + 1]);
        float res[8];
#pragma unroll
        for (int v = 0; v < 8; v++) {
            float x = fmaxf(nai[u] + naj[v] - 2.0f * g[v], 1e-6f);
            float d = x * rsqf(x);            // sqrt(x), x >= 1e-6
            float val = ex2f(c * d) * mi[u] * mj[v];
            res[v] = fminf(val, 1.0f);
        }
        float4* p = (float4*)(dout + (i0 + u) * BS + j0);
        p[0] = make_float4(res[0], res[1], res[2], res[3]);
        p[1] = make_float4(res[4], res[5], res[6], res[7]);
    }

    // Fused x_node gather: this bin's 128 rows of 256 floats (64 float4).
    const float4* xn = x_node4 + (size_t)b * NN * (FN / 4);
    float4* xo = (float4*)(out + OFF_XNODE) + (size_t)blockIdx.x * BS * (FN / 4);
    for (int r = w; r < BS; r += 8) {
        int src = gb[r];
        const float4* s = xn + (size_t)src * (FN / 4);
        float4* d = xo + (size_t)r * (FN / 4);
#pragma unroll
        for (int c4 = 0; c4 < 2; c4++) d[lane + 32 * c4] = s[lane + 32 * c4];
    }
}

// ---------------------------------------------------------------------------
extern "C" void kernel_launch(void* const* d_in, const int* in_sizes, int n_in,
                              void* d_out, int out_size) {
    const float* x_msg  = (const float*)d_in[0];
    const float* x_node = (const float*)d_in[1];
    const int*   msk    = (const int*)d_in[2];
    const float* rot    = (const float*)d_in[3];
    float* out = (float*)d_out;

    const int SM2 = NKEYS * 128 * 2;                // 51200
    const int SM4 = 128 * ST * 4 + 2 * 128 * 4;     // 68608
    cudaFuncSetAttribute(k_sort, cudaFuncAttributeMaxDynamicSharedMemorySize, SM2);
    cudaFuncSetAttribute(k_dm,   cudaFuncAttributeMaxDynamicSharedMemorySize, SM4);

    k_proj<<<BB * (NN / 128), 128>>>(x_msg, msk, rot);
    k_sort<<<BB, 128, SM2>>>(msk, out);
    k_dm<<<BB * NBINS, 256, SM4>>>((const float4*)x_msg, msk,
                                   (const float4*)x_node, out);
}

// round 7
// speedup vs baseline: 1.7713x; 1.0452x over previous
#include <cuda_runtime.h>
#include <cstdint>

// Problem constants
#define BB 16
#define NN 12800
#define FM 128          // F_MSG
#define FN 256          // F_NODE
#define NBINS 100       // N / BIN_SIZE
#define HB 50           // NBINS / 2
#define BS 128          // BIN_SIZE
#define NKEYS 200       // bin keys in [0, 198]
#define ROTC 100        // rot second-dim stride (MAX_NUM_BINS/2)

// Output layout (flattened float32, reference tuple order)
#define OFF_BINS   0
#define LEN_BINS   (BB * NN)                  // 204800
#define OFF_XNODE  (OFF_BINS + LEN_BINS)      // 204800
#define LEN_XNODE  (BB * NN * FN)             // 52428800
#define OFF_DM     (OFF_XNODE + LEN_XNODE)    // 52633600
#define LEN_DM     (BB * NN * BS)             // 26214400
#define OFF_MSKF   (OFF_DM + LEN_DM)          // 78848000

// Scratch (device globals: no allocation allowed)
__device__ int g_key[BB * NN];    // bin key per (b,n)
__device__ int g_bins[BB * NN];   // sorted original indices (bins_split)

typedef unsigned long long u64;

__device__ __forceinline__ float ex2f(float x) {
    float y; asm("ex2.approx.f32 %0, %1;" : "=f"(y) : "f"(x)); return y;
}
__device__ __forceinline__ float rsqf(float x) {
    float y; asm("rsqrt.approx.f32 %0, %1;" : "=f"(y) : "f"(x)); return y;
}
// packed fp32x2 helpers (bit-exact per-lane IEEE fp32 FMA)
__device__ __forceinline__ u64 pack2(float x, float y) {
    u64 r; asm("mov.b64 %0, {%1, %2};" : "=l"(r) : "f"(x), "f"(y)); return r;
}
__device__ __forceinline__ void unpack2(u64 v, float& x, float& y) {
    asm("mov.b64 {%0, %1}, %2;" : "=f"(x), "=f"(y) : "l"(v));
}
__device__ __forceinline__ void fma2(u64& d, u64 a, u64 b) {
    asm("fma.rn.f32x2 %0, %1, %2, %0;" : "+l"(d) : "l"(a), "l"(b));
}

// ---------------------------------------------------------------------------
// K1: LSH projection + argmax -> bin key.  Register-tiled GEMM. (unchanged)
// ---------------------------------------------------------------------------
__global__ void __launch_bounds__(128, 4)
k_proj(const float* __restrict__ x_msg,
       const int* __restrict__ msk,
       const float* __restrict__ rot) {
    const int b  = blockIdx.x / (NN / 128);
    const int n0 = (blockIdx.x % (NN / 128)) * 128;
    __shared__ float Rs[128 * 64];
    const int tid = threadIdx.x;
    const int jx = tid & 7;
    const int iy = tid >> 3;

    for (int idx = tid; idx < 128 * 64; idx += 128) {
        int f = idx >> 6, hp = idx & 63;
        int half = hp >> 5;
        int g    = (hp & 31) >> 2;
        int e    = (hp & 3) + half * 4;
        int h    = g * 8 + e;
        Rs[idx] = (h < HB) ? rot[f * ROTC + h] : 0.f;
    }
    __syncthreads();

    u64 acc[8][4];
#pragma unroll
    for (int k = 0; k < 8; k++)
#pragma unroll
        for (int p = 0; p < 4; p++) acc[k][p] = pack2(0.f, 0.f);

    const float4* xb4 = (const float4*)(x_msg + ((size_t)b * NN + n0) * FM);
    for (int f4 = 0; f4 < FM / 4; f4++) {
        float4 av[8];
#pragma unroll
        for (int k = 0; k < 8; k++)
            av[k] = xb4[(size_t)(iy * 8 + k) * (FM / 4) + f4];
#pragma unroll
        for (int ff = 0; ff < 4; ff++) {
            const float* rrow = Rs + (f4 * 4 + ff) * 64;
            ulonglong2 q0 = *(const ulonglong2*)(rrow + jx * 4);
            ulonglong2 q1 = *(const ulonglong2*)(rrow + 32 + jx * 4);
#pragma unroll
            for (int k = 0; k < 8; k++) {
                float a = (ff == 0) ? av[k].x : (ff == 1) ? av[k].y
                         : (ff == 2) ? av[k].z : av[k].w;
                u64 a2 = pack2(a, a);
                fma2(acc[k][0], a2, q0.x);
                fma2(acc[k][1], a2, q0.y);
                fma2(acc[k][2], a2, q1.x);
                fma2(acc[k][3], a2, q1.y);
            }
        }
    }

#pragma unroll
    for (int k = 0; k < 8; k++) {
        float v[8];
#pragma unroll
        for (int p = 0; p < 4; p++) unpack2(acc[k][p], v[2 * p], v[2 * p + 1]);
        float bv = v[0]; int bh = jx * 8;
        float mv = v[0]; int mh = jx * 8;
#pragma unroll
        for (int e = 1; e < 8; e++) {
            int h = jx * 8 + e;
            if (v[e] > bv) { bv = v[e]; bh = h; }
            if (v[e] < mv) { mv = v[e]; mh = h; }
        }
#pragma unroll
        for (int off = 1; off < 8; off <<= 1) {
            float obv = __shfl_xor_sync(0xffffffffu, bv, off);
            int   obh = __shfl_xor_sync(0xffffffffu, bh, off);
            float omv = __shfl_xor_sync(0xffffffffu, mv, off);
            int   omh = __shfl_xor_sync(0xffffffffu, mh, off);
            if (obv > bv || (obv == bv && obh < bh)) { bv = obv; bh = obh; }
            if (omv < mv || (omv == mv && omh < mh)) { mv = omv; mh = omh; }
        }
        if (jx == 0) {
            int idx = (bv >= -mv) ? bh : (HB + mh);
            int n = n0 + iy * 8 + k;
            int m = msk[(size_t)b * NN + n];
            g_key[(size_t)b * NN + n] = idx + (m ? 0 : (NBINS - 1));
        }
    }
}

// ---------------------------------------------------------------------------
// K2: stable counting sort per batch (unchanged).
// ---------------------------------------------------------------------------
__global__ void k_sort(const int* __restrict__ msk,
                       float* __restrict__ out) {
    const int b = blockIdx.x;
    extern __shared__ unsigned short off[];        // [NKEYS][128]
    __shared__ unsigned int keyTotal[NKEYS];
    __shared__ unsigned int keyBase[NKEYS];
    const int t = threadIdx.x;

    for (int i = t; i < NKEYS * 128; i += 128) off[i] = 0;
    __syncthreads();

    const int* kb = g_key + (size_t)b * NN;
    const int base_n = t * 100;
    for (int q = 0; q < 100; q++) {
        int k = kb[base_n + q];
        off[k * 128 + t]++;
    }
    __syncthreads();

    for (int k = t; k < NKEYS; k += 128) {
        unsigned int run = 0;
        for (int tt = 0; tt < 128; tt++) {
            unsigned short c = off[k * 128 + tt];
            off[k * 128 + tt] = (unsigned short)run;
            run += c;
        }
        keyTotal[k] = run;
    }
    __syncthreads();
    if (t == 0) {
        unsigned int run = 0;
        for (int k = 0; k < NKEYS; k++) { keyBase[k] = run; run += keyTotal[k]; }
    }
    __syncthreads();

    int* gb = g_bins + (size_t)b * NN;
    const int* mb = msk + (size_t)b * NN;
    float* out_bins = out + OFF_BINS + (size_t)b * NN;
    float* out_mskf = out + OFF_MSKF + (size_t)b * NN;
    for (int q = 0; q < 100; q++) {
        int n = base_n + q;
        int k = kb[n];
        unsigned int pos = keyBase[k] + off[k * 128 + t];
        off[k * 128 + t]++;
        gb[pos] = n;
        out_bins[pos] = (float)n;
        out_mskf[pos] = mb[n] ? 1.0f : 0.0f;
    }
}

// ---------------------------------------------------------------------------
// K4: per-bin pairwise gaussian kernel + fused x_node gather.
// Symmetric gram: only 136 upper-triangle 8x8 tiles computed (threads 0..135,
// bitwise-identical op order to full version); each writes its tile AND the
// transposed mirror, both row-major/coalesced. Warps 5-7 start the x_node
// gather immediately, overlapping gram compute; compute warps join after.
// occ=2 (regs~94; capping to 84 spills accumulators -> R4 regression).
// ---------------------------------------------------------------------------
#define ST 132
__global__ void __launch_bounds__(256, 2)
k_dm(const float4* __restrict__ x_msg4,
     const int* __restrict__ msk,
     const float4* __restrict__ x_node4,
     float* __restrict__ out) {
    const int b   = blockIdx.x / NBINS;
    const int bin = blockIdx.x % NBINS;
    extern __shared__ float sm4[];
    float* As = sm4;                 // [128][ST], f-major (A transposed)
    float* na = sm4 + 128 * ST;      // [128]
    float* mm = na + 128;            // [128]
    const int tid  = threadIdx.x;    // 256
    const int w    = tid >> 5;
    const int lane = tid & 31;

    const int* gb = g_bins + ((size_t)b * NBINS + bin) * BS;
    const float4* xb = x_msg4 + (size_t)b * NN * (FM / 4);
    for (int r = w; r < BS; r += 8) {
        int src = gb[r];
        float m = msk[(size_t)b * NN + src] ? 1.f : 0.f;
        float4 v = xb[(size_t)src * (FM / 4) + lane];
        v.x *= m; v.y *= m; v.z *= m; v.w *= m;
        As[(4 * lane + 0) * ST + r] = v.x;
        As[(4 * lane + 1) * ST + r] = v.y;
        As[(4 * lane + 2) * ST + r] = v.z;
        As[(4 * lane + 3) * ST + r] = v.w;
        float s = v.x * v.x + v.y * v.y + v.z * v.z + v.w * v.w;
#pragma unroll
        for (int o = 16; o; o >>= 1) s += __shfl_xor_sync(0xffffffffu, s, o);
        if (lane == 0) { na[r] = s; mm[r] = m; }
    }
    __syncthreads();

    if (tid < 136) {
        // map tid -> (ty, tx) in upper triangle (tx >= ty) of 16x16 tile grid
        int ty = 0, rem = tid;
        while (rem >= 16 - ty) { rem -= 16 - ty; ty++; }
        const int tx = ty + rem;
        const int i0 = ty * 8, j0 = tx * 8;

        u64 acc2[8][4];
#pragma unroll
        for (int u = 0; u < 8; u++)
#pragma unroll
            for (int v = 0; v < 4; v++) acc2[u][v] = pack2(0.f, 0.f);

        for (int f = 0; f < FM; f++) {
            const float* row = As + f * ST;
            float4 a0 = *(const float4*)(row + i0);
            float4 a1 = *(const float4*)(row + i0 + 4);
            ulonglong2 q0 = *(const ulonglong2*)(row + j0);
            ulonglong2 q1 = *(const ulonglong2*)(row + j0 + 4);
            float a[8] = {a0.x, a0.y, a0.z, a0.w, a1.x, a1.y, a1.z, a1.w};
            u64 bq[4] = {q0.x, q0.y, q1.x, q1.y};
#pragma unroll
            for (int u = 0; u < 8; u++) {
                u64 au = pack2(a[u], a[u]);
#pragma unroll
                for (int v = 0; v < 4; v++) fma2(acc2[u][v], au, bq[v]);
            }
        }

        float nai[8], mi[8], naj[8], mj[8];
#pragma unroll
        for (int u = 0; u < 8; u++) { nai[u] = na[i0 + u]; mi[u] = mm[i0 + u]; }
#pragma unroll
        for (int v = 0; v < 8; v++) { naj[v] = na[j0 + v]; mj[v] = mm[j0 + v]; }

        float* dout = out + OFF_DM + (size_t)blockIdx.x * BS * BS;
        const float c = -0.14426950408889634f;   // -DIST_MULT * log2(e)
        float res[8][8];
#pragma unroll
        for (int u = 0; u < 8; u++) {
            float g[8];
#pragma unroll
            for (int v = 0; v < 4; v++) unpack2(acc2[u][v], g[2 * v], g[2 * v + 1]);
#pragma unroll
            for (int v = 0; v < 8; v++) {
                float x = fmaxf(nai[u] + naj[v] - 2.0f * g[v], 1e-6f);
                float d = x * rsqf(x);            // sqrt(x), x >= 1e-6
                float val = ex2f(c * d) * mi[u] * mj[v];
                res[u][v] = fminf(val, 1.0f);
            }
        }
        // tile (i0, j0)
#pragma unroll
        for (int u = 0; u < 8; u++) {
            float4* p = (float4*)(dout + (size_t)(i0 + u) * BS + j0);
            p[0] = make_float4(res[u][0], res[u][1], res[u][2], res[u][3]);
            p[1] = make_float4(res[u][4], res[u][5], res[u][6], res[u][7]);
        }
        // mirrored tile (j0, i0) — dm is exactly symmetric
        if (tx != ty) {
#pragma unroll
            for (int v = 0; v < 8; v++) {
                float4* p = (float4*)(dout + (size_t)(j0 + v) * BS + i0);
                p[0] = make_float4(res[0][v], res[1][v], res[2][v], res[3][v]);
                p[1] = make_float4(res[4][v], res[5][v], res[6][v], res[7][v]);
            }
        }
    }

    // Fused x_node gather: this bin's 128 rows of 256 floats (64 float4).
    // Warps 5-7 reach here immediately (overlap with gram); warps 0-4 after.
    const float4* xn = x_node4 + (size_t)b * NN * (FN / 4);
    float4* xo = (float4*)(out + OFF_XNODE) + (size_t)blockIdx.x * BS * (FN / 4);
    for (int r = w; r < BS; r += 8) {
        int src = gb[r];
        const float4* s = xn + (size_t)src * (FN / 4);
        float4* d = xo + (size_t)r * (FN / 4);
#pragma unroll
        for (int c4 = 0; c4 < 2; c4++) d[lane + 32 * c4] = s[lane + 32 * c4];
    }
}

// ---------------------------------------------------------------------------
extern "C" void kernel_launch(void* const* d_in, const int* in_sizes, int n_in,
                              void* d_out, int out_size) {
    const float* x_msg  = (const float*)d_in[0];
    const float* x_node = (const float*)d_in[1];
    const int*   msk    = (const int*)d_in[2];
    const float* rot    = (const float*)d_in[3];
    float* out = (float*)d_out;

    const int SM2 = NKEYS * 128 * 2;                // 51200
    const int SM4 = 128 * ST * 4 + 2 * 128 * 4;     // 68608
    cudaFuncSetAttribute(k_sort, cudaFuncAttributeMaxDynamicSharedMemorySize, SM2);
    cudaFuncSetAttribute(k_dm,   cudaFuncAttributeMaxDynamicSharedMemorySize, SM4);

    k_proj<<<BB * (NN / 128), 128>>>(x_msg, msk, rot);
    k_sort<<<BB, 128, SM2>>>(msk, out);
    k_dm<<<BB * NBINS, 256, SM4>>>((const float4*)x_msg, msk,
                                   (const float4*)x_node, out);
}

// round 8
// speedup vs baseline: 2.1200x; 1.1969x over previous
#include <cuda_runtime.h>
#include <cstdint>

// Problem constants
#define BB 16
#define NN 12800
#define FM 128          // F_MSG
#define FN 256          // F_NODE
#define NBINS 100       // N / BIN_SIZE
#define HB 50           // NBINS / 2
#define BS 128          // BIN_SIZE
#define NKEYS 200       // bin keys in [0, 198]
#define ROTC 100        // rot second-dim stride (MAX_NUM_BINS/2)

// Output layout (flattened float32, reference tuple order)
#define OFF_BINS   0
#define LEN_BINS   (BB * NN)                  // 204800
#define OFF_XNODE  (OFF_BINS + LEN_BINS)      // 204800
#define LEN_XNODE  (BB * NN * FN)             // 52428800
#define OFF_DM     (OFF_XNODE + LEN_XNODE)    // 52633600
#define LEN_DM     (BB * NN * BS)             // 26214400
#define OFF_MSKF   (OFF_DM + LEN_DM)          // 78848000

// Scratch (device globals: no allocation allowed)
__device__ int g_key[BB * NN];    // bin key per (b,n)
__device__ int g_bins[BB * NN];   // sorted original indices (bins_split)

typedef unsigned long long u64;

__device__ __forceinline__ float ex2f(float x) {
    float y; asm("ex2.approx.f32 %0, %1;" : "=f"(y) : "f"(x)); return y;
}
__device__ __forceinline__ float rsqf(float x) {
    float y; asm("rsqrt.approx.f32 %0, %1;" : "=f"(y) : "f"(x)); return y;
}
// packed fp32x2 helpers (bit-exact per-lane IEEE fp32 FMA)
__device__ __forceinline__ u64 pack2(float x, float y) {
    u64 r; asm("mov.b64 %0, {%1, %2};" : "=l"(r) : "f"(x), "f"(y)); return r;
}
__device__ __forceinline__ void unpack2(u64 v, float& x, float& y) {
    asm("mov.b64 {%0, %1}, %2;" : "=f"(x), "=f"(y) : "l"(v));
}
__device__ __forceinline__ void fma2(u64& d, u64 a, u64 b) {
    asm("fma.rn.f32x2 %0, %1, %2, %0;" : "+l"(d) : "l"(a), "l"(b));
}

// ---------------------------------------------------------------------------
// K1: LSH projection + argmax -> bin key.  Register-tiled GEMM. (unchanged)
// ---------------------------------------------------------------------------
__global__ void __launch_bounds__(128, 4)
k_proj(const float* __restrict__ x_msg,
       const int* __restrict__ msk,
       const float* __restrict__ rot) {
    const int b  = blockIdx.x / (NN / 128);
    const int n0 = (blockIdx.x % (NN / 128)) * 128;
    __shared__ float Rs[128 * 64];
    const int tid = threadIdx.x;
    const int jx = tid & 7;
    const int iy = tid >> 3;

    for (int idx = tid; idx < 128 * 64; idx += 128) {
        int f = idx >> 6, hp = idx & 63;
        int half = hp >> 5;
        int g    = (hp & 31) >> 2;
        int e    = (hp & 3) + half * 4;
        int h    = g * 8 + e;
        Rs[idx] = (h < HB) ? rot[f * ROTC + h] : 0.f;
    }
    __syncthreads();

    u64 acc[8][4];
#pragma unroll
    for (int k = 0; k < 8; k++)
#pragma unroll
        for (int p = 0; p < 4; p++) acc[k][p] = pack2(0.f, 0.f);

    const float4* xb4 = (const float4*)(x_msg + ((size_t)b * NN + n0) * FM);
    for (int f4 = 0; f4 < FM / 4; f4++) {
        float4 av[8];
#pragma unroll
        for (int k = 0; k < 8; k++)
            av[k] = xb4[(size_t)(iy * 8 + k) * (FM / 4) + f4];
#pragma unroll
        for (int ff = 0; ff < 4; ff++) {
            const float* rrow = Rs + (f4 * 4 + ff) * 64;
            ulonglong2 q0 = *(const ulonglong2*)(rrow + jx * 4);
            ulonglong2 q1 = *(const ulonglong2*)(rrow + 32 + jx * 4);
#pragma unroll
            for (int k = 0; k < 8; k++) {
                float a = (ff == 0) ? av[k].x : (ff == 1) ? av[k].y
                         : (ff == 2) ? av[k].z : av[k].w;
                u64 a2 = pack2(a, a);
                fma2(acc[k][0], a2, q0.x);
                fma2(acc[k][1], a2, q0.y);
                fma2(acc[k][2], a2, q1.x);
                fma2(acc[k][3], a2, q1.y);
            }
        }
    }

#pragma unroll
    for (int k = 0; k < 8; k++) {
        float v[8];
#pragma unroll
        for (int p = 0; p < 4; p++) unpack2(acc[k][p], v[2 * p], v[2 * p + 1]);
        float bv = v[0]; int bh = jx * 8;
        float mv = v[0]; int mh = jx * 8;
#pragma unroll
        for (int e = 1; e < 8; e++) {
            int h = jx * 8 + e;
            if (v[e] > bv) { bv = v[e]; bh = h; }
            if (v[e] < mv) { mv = v[e]; mh = h; }
        }
#pragma unroll
        for (int off = 1; off < 8; off <<= 1) {
            float obv = __shfl_xor_sync(0xffffffffu, bv, off);
            int   obh = __shfl_xor_sync(0xffffffffu, bh, off);
            float omv = __shfl_xor_sync(0xffffffffu, mv, off);
            int   omh = __shfl_xor_sync(0xffffffffu, mh, off);
            if (obv > bv || (obv == bv && obh < bh)) { bv = obv; bh = obh; }
            if (omv < mv || (omv == mv && omh < mh)) { mv = omv; mh = omh; }
        }
        if (jx == 0) {
            int idx = (bv >= -mv) ? bh : (HB + mh);
            int n = n0 + iy * 8 + k;
            int m = msk[(size_t)b * NN + n];
            g_key[(size_t)b * NN + n] = idx + (m ? 0 : (NBINS - 1));
        }
    }
}

// ---------------------------------------------------------------------------
// K2: stable counting sort per batch (unchanged).
// ---------------------------------------------------------------------------
__global__ void k_sort(const int* __restrict__ msk,
                       float* __restrict__ out) {
    const int b = blockIdx.x;
    extern __shared__ unsigned short off[];        // [NKEYS][128]
    __shared__ unsigned int keyTotal[NKEYS];
    __shared__ unsigned int keyBase[NKEYS];
    const int t = threadIdx.x;

    for (int i = t; i < NKEYS * 128; i += 128) off[i] = 0;
    __syncthreads();

    const int* kb = g_key + (size_t)b * NN;
    const int base_n = t * 100;
    for (int q = 0; q < 100; q++) {
        int k = kb[base_n + q];
        off[k * 128 + t]++;
    }
    __syncthreads();

    for (int k = t; k < NKEYS; k += 128) {
        unsigned int run = 0;
        for (int tt = 0; tt < 128; tt++) {
            unsigned short c = off[k * 128 + tt];
            off[k * 128 + tt] = (unsigned short)run;
            run += c;
        }
        keyTotal[k] = run;
    }
    __syncthreads();
    if (t == 0) {
        unsigned int run = 0;
        for (int k = 0; k < NKEYS; k++) { keyBase[k] = run; run += keyTotal[k]; }
    }
    __syncthreads();

    int* gb = g_bins + (size_t)b * NN;
    const int* mb = msk + (size_t)b * NN;
    float* out_bins = out + OFF_BINS + (size_t)b * NN;
    float* out_mskf = out + OFF_MSKF + (size_t)b * NN;
    for (int q = 0; q < 100; q++) {
        int n = base_n + q;
        int k = kb[n];
        unsigned int pos = keyBase[k] + off[k * 128 + t];
        off[k * 128 + t]++;
        gb[pos] = n;
        out_bins[pos] = (float)n;
        out_mskf[pos] = mb[n] ? 1.0f : 0.0f;
    }
}

// ---------------------------------------------------------------------------
// K4: per-bin pairwise gaussian kernel + fused x_node gather.
// 512 threads. Symmetric gram: 136 upper-triangle 8x8 tiles split into 272
// 8x4 half-tiles on threads 0..271 (bitwise-identical op order); warps 9-15
// fall straight through to the x_node gather (overlap). Mirror writes for
// off-diag tiles. na/mm re-read from smem in epilogue (register cap 64).
// ---------------------------------------------------------------------------
#define ST 132
__global__ void __launch_bounds__(512, 2)
k_dm(const float4* __restrict__ x_msg4,
     const int* __restrict__ msk,
     const float4* __restrict__ x_node4,
     float* __restrict__ out) {
    const int b   = blockIdx.x / NBINS;
    const int bin = blockIdx.x % NBINS;
    extern __shared__ float sm4[];
    float* As = sm4;                 // [128][ST], f-major (A transposed)
    float* na = sm4 + 128 * ST;      // [128]
    float* mm = na + 128;            // [128]
    const int tid  = threadIdx.x;    // 512
    const int w    = tid >> 5;       // 0..15
    const int lane = tid & 31;

    const int* gb = g_bins + ((size_t)b * NBINS + bin) * BS;
    const float4* xb = x_msg4 + (size_t)b * NN * (FM / 4);
    for (int r = w; r < BS; r += 16) {
        int src = gb[r];
        float m = msk[(size_t)b * NN + src] ? 1.f : 0.f;
        float4 v = xb[(size_t)src * (FM / 4) + lane];
        v.x *= m; v.y *= m; v.z *= m; v.w *= m;
        As[(4 * lane + 0) * ST + r] = v.x;
        As[(4 * lane + 1) * ST + r] = v.y;
        As[(4 * lane + 2) * ST + r] = v.z;
        As[(4 * lane + 3) * ST + r] = v.w;
        float s = v.x * v.x + v.y * v.y + v.z * v.z + v.w * v.w;
#pragma unroll
        for (int o = 16; o; o >>= 1) s += __shfl_xor_sync(0xffffffffu, s, o);
        if (lane == 0) { na[r] = s; mm[r] = m; }
    }
    __syncthreads();

    if (tid < 272) {
        const int tile = tid >> 1;
        const int half = tid & 1;
        // map tile -> (ty, tx) in upper triangle (tx >= ty) of 16x16 grid
        int ty = 0, rem = tile;
        while (rem >= 16 - ty) { rem -= 16 - ty; ty++; }
        const int tx = ty + rem;
        const int i0 = ty * 8;
        const int j0 = tx * 8 + half * 4;   // 4-col half

        u64 acc2[8][2];
#pragma unroll
        for (int u = 0; u < 8; u++) {
            acc2[u][0] = pack2(0.f, 0.f);
            acc2[u][1] = pack2(0.f, 0.f);
        }

        for (int f = 0; f < FM; f++) {
            const float* row = As + f * ST;
            float4 a0 = *(const float4*)(row + i0);
            float4 a1 = *(const float4*)(row + i0 + 4);
            ulonglong2 q = *(const ulonglong2*)(row + j0);   // (c0,c1),(c2,c3)
            float a[8] = {a0.x, a0.y, a0.z, a0.w, a1.x, a1.y, a1.z, a1.w};
#pragma unroll
            for (int u = 0; u < 8; u++) {
                u64 au = pack2(a[u], a[u]);
                fma2(acc2[u][0], au, q.x);
                fma2(acc2[u][1], au, q.y);
            }
        }

        float* dout = out + OFF_DM + (size_t)blockIdx.x * BS * BS;
        const float c = -0.14426950408889634f;   // -DIST_MULT * log2(e)
        float res[8][4];
#pragma unroll
        for (int u = 0; u < 8; u++) {
            float g[4];
            unpack2(acc2[u][0], g[0], g[1]);
            unpack2(acc2[u][1], g[2], g[3]);
            const float nai = na[i0 + u];
            const float mi  = mm[i0 + u];
#pragma unroll
            for (int v = 0; v < 4; v++) {
                float x = fmaxf(nai + na[j0 + v] - 2.0f * g[v], 1e-6f);
                float d = x * rsqf(x);            // sqrt(x), x >= 1e-6
                float val = ex2f(c * d) * mi * mm[j0 + v];
                res[u][v] = fminf(val, 1.0f);
            }
            *(float4*)(dout + (size_t)(i0 + u) * BS + j0) =
                make_float4(res[u][0], res[u][1], res[u][2], res[u][3]);
        }
        // mirrored 4x8 block at (j0.., i0..) — dm is exactly symmetric
        if (tx != ty) {
#pragma unroll
            for (int v = 0; v < 4; v++) {
                float4* p = (float4*)(dout + (size_t)(j0 + v) * BS + i0);
                p[0] = make_float4(res[0][v], res[1][v], res[2][v], res[3][v]);
                p[1] = make_float4(res[4][v], res[5][v], res[6][v], res[7][v]);
            }
        }
    }

    // Fused x_node gather: 128 rows of 256 floats (64 float4 each).
    // Warps 9-15 reach here immediately (overlap with gram); rest after.
    const float4* xn = x_node4 + (size_t)b * NN * (FN / 4);
    float4* xo = (float4*)(out + OFF_XNODE) + (size_t)blockIdx.x * BS * (FN / 4);
    for (int r = w; r < BS; r += 16) {
        int src = gb[r];
        const float4* s = xn + (size_t)src * (FN / 4);
        float4* d = xo + (size_t)r * (FN / 4);
#pragma unroll
        for (int c4 = 0; c4 < 2; c4++) d[lane + 32 * c4] = s[lane + 32 * c4];
    }
}

// ---------------------------------------------------------------------------
extern "C" void kernel_launch(void* const* d_in, const int* in_sizes, int n_in,
                              void* d_out, int out_size) {
    const float* x_msg  = (const float*)d_in[0];
    const float* x_node = (const float*)d_in[1];
    const int*   msk    = (const int*)d_in[2];
    const float* rot    = (const float*)d_in[3];
    float* out = (float*)d_out;

    const int SM2 = NKEYS * 128 * 2;                // 51200
    const int SM4 = 128 * ST * 4 + 2 * 128 * 4;     // 68608
    cudaFuncSetAttribute(k_sort, cudaFuncAttributeMaxDynamicSharedMemorySize, SM2);
    cudaFuncSetAttribute(k_dm,   cudaFuncAttributeMaxDynamicSharedMemorySize, SM4);

    k_proj<<<BB * (NN / 128), 128>>>(x_msg, msk, rot);
    k_sort<<<BB, 128, SM2>>>(msk, out);
    k_dm<<<BB * NBINS, 512, SM4>>>((const float4*)x_msg, msk,
                                   (const float4*)x_node, out);
}

// round 9
// speedup vs baseline: 2.4224x; 1.1426x over previous
#include <cuda_runtime.h>
#include <cstdint>

// Problem constants
#define BB 16
#define NN 12800
#define FM 128          // F_MSG
#define FN 256          // F_NODE
#define NBINS 100       // N / BIN_SIZE
#define HB 50           // NBINS / 2
#define BS 128          // BIN_SIZE
#define NKEYS 200       // bin keys in [0, 198]
#define ROTC 100        // rot second-dim stride (MAX_NUM_BINS/2)

// Output layout (flattened float32, reference tuple order)
#define OFF_BINS   0
#define LEN_BINS   (BB * NN)                  // 204800
#define OFF_XNODE  (OFF_BINS + LEN_BINS)      // 204800
#define LEN_XNODE  (BB * NN * FN)             // 52428800
#define OFF_DM     (OFF_XNODE + LEN_XNODE)    // 52633600
#define LEN_DM     (BB * NN * BS)             // 26214400
#define OFF_MSKF   (OFF_DM + LEN_DM)          // 78848000

// Scratch (device globals: no allocation allowed)
__device__ int g_key[BB * NN];    // bin key per (b,n)
__device__ int g_bins[BB * NN];   // sorted original indices (bins_split)

typedef unsigned long long u64;

__device__ __forceinline__ float ex2f(float x) {
    float y; asm("ex2.approx.f32 %0, %1;" : "=f"(y) : "f"(x)); return y;
}
__device__ __forceinline__ float rsqf(float x) {
    float y; asm("rsqrt.approx.f32 %0, %1;" : "=f"(y) : "f"(x)); return y;
}
// packed fp32x2 helpers (bit-exact per-lane IEEE fp32 FMA)
__device__ __forceinline__ u64 pack2(float x, float y) {
    u64 r; asm("mov.b64 %0, {%1, %2};" : "=l"(r) : "f"(x), "f"(y)); return r;
}
__device__ __forceinline__ void unpack2(u64 v, float& x, float& y) {
    asm("mov.b64 {%0, %1}, %2;" : "=f"(x), "=f"(y) : "l"(v));
}
__device__ __forceinline__ void fma2(u64& d, u64 a, u64 b) {
    asm("fma.rn.f32x2 %0, %1, %2, %0;" : "+l"(d) : "l"(a), "l"(b));
}

// ---------------------------------------------------------------------------
// K1: LSH projection + argmax -> bin key.  Register-tiled GEMM. (unchanged)
// ---------------------------------------------------------------------------
__global__ void __launch_bounds__(128, 4)
k_proj(const float* __restrict__ x_msg,
       const int* __restrict__ msk,
       const float* __restrict__ rot) {
    const int b  = blockIdx.x / (NN / 128);
    const int n0 = (blockIdx.x % (NN / 128)) * 128;
    __shared__ float Rs[128 * 64];
    const int tid = threadIdx.x;
    const int jx = tid & 7;
    const int iy = tid >> 3;

    for (int idx = tid; idx < 128 * 64; idx += 128) {
        int f = idx >> 6, hp = idx & 63;
        int half = hp >> 5;
        int g    = (hp & 31) >> 2;
        int e    = (hp & 3) + half * 4;
        int h    = g * 8 + e;
        Rs[idx] = (h < HB) ? rot[f * ROTC + h] : 0.f;
    }
    __syncthreads();

    u64 acc[8][4];
#pragma unroll
    for (int k = 0; k < 8; k++)
#pragma unroll
        for (int p = 0; p < 4; p++) acc[k][p] = pack2(0.f, 0.f);

    const float4* xb4 = (const float4*)(x_msg + ((size_t)b * NN + n0) * FM);
    for (int f4 = 0; f4 < FM / 4; f4++) {
        float4 av[8];
#pragma unroll
        for (int k = 0; k < 8; k++)
            av[k] = xb4[(size_t)(iy * 8 + k) * (FM / 4) + f4];
#pragma unroll
        for (int ff = 0; ff < 4; ff++) {
            const float* rrow = Rs + (f4 * 4 + ff) * 64;
            ulonglong2 q0 = *(const ulonglong2*)(rrow + jx * 4);
            ulonglong2 q1 = *(const ulonglong2*)(rrow + 32 + jx * 4);
#pragma unroll
            for (int k = 0; k < 8; k++) {
                float a = (ff == 0) ? av[k].x : (ff == 1) ? av[k].y
                         : (ff == 2) ? av[k].z : av[k].w;
                u64 a2 = pack2(a, a);
                fma2(acc[k][0], a2, q0.x);
                fma2(acc[k][1], a2, q0.y);
                fma2(acc[k][2], a2, q1.x);
                fma2(acc[k][3], a2, q1.y);
            }
        }
    }

#pragma unroll
    for (int k = 0; k < 8; k++) {
        float v[8];
#pragma unroll
        for (int p = 0; p < 4; p++) unpack2(acc[k][p], v[2 * p], v[2 * p + 1]);
        float bv = v[0]; int bh = jx * 8;
        float mv = v[0]; int mh = jx * 8;
#pragma unroll
        for (int e = 1; e < 8; e++) {
            int h = jx * 8 + e;
            if (v[e] > bv) { bv = v[e]; bh = h; }
            if (v[e] < mv) { mv = v[e]; mh = h; }
        }
#pragma unroll
        for (int off = 1; off < 8; off <<= 1) {
            float obv = __shfl_xor_sync(0xffffffffu, bv, off);
            int   obh = __shfl_xor_sync(0xffffffffu, bh, off);
            float omv = __shfl_xor_sync(0xffffffffu, mv, off);
            int   omh = __shfl_xor_sync(0xffffffffu, mh, off);
            if (obv > bv || (obv == bv && obh < bh)) { bv = obv; bh = obh; }
            if (omv < mv || (omv == mv && omh < mh)) { mv = omv; mh = omh; }
        }
        if (jx == 0) {
            int idx = (bv >= -mv) ? bh : (HB + mh);
            int n = n0 + iy * 8 + k;
            int m = msk[(size_t)b * NN + n];
            g_key[(size_t)b * NN + n] = idx + (m ? 0 : (NBINS - 1));
        }
    }
}

// ---------------------------------------------------------------------------
// K2: stable counting sort per batch (unchanged).
// ---------------------------------------------------------------------------
__global__ void k_sort(const int* __restrict__ msk,
                       float* __restrict__ out) {
    const int b = blockIdx.x;
    extern __shared__ unsigned short off[];        // [NKEYS][128]
    __shared__ unsigned int keyTotal[NKEYS];
    __shared__ unsigned int keyBase[NKEYS];
    const int t = threadIdx.x;

    for (int i = t; i < NKEYS * 128; i += 128) off[i] = 0;
    __syncthreads();

    const int* kb = g_key + (size_t)b * NN;
    const int base_n = t * 100;
    for (int q = 0; q < 100; q++) {
        int k = kb[base_n + q];
        off[k * 128 + t]++;
    }
    __syncthreads();

    for (int k = t; k < NKEYS; k += 128) {
        unsigned int run = 0;
        for (int tt = 0; tt < 128; tt++) {
            unsigned short c = off[k * 128 + tt];
            off[k * 128 + tt] = (unsigned short)run;
            run += c;
        }
        keyTotal[k] = run;
    }
    __syncthreads();
    if (t == 0) {
        unsigned int run = 0;
        for (int k = 0; k < NKEYS; k++) { keyBase[k] = run; run += keyTotal[k]; }
    }
    __syncthreads();

    int* gb = g_bins + (size_t)b * NN;
    const int* mb = msk + (size_t)b * NN;
    float* out_bins = out + OFF_BINS + (size_t)b * NN;
    float* out_mskf = out + OFF_MSKF + (size_t)b * NN;
    for (int q = 0; q < 100; q++) {
        int n = base_n + q;
        int k = kb[n];
        unsigned int pos = keyBase[k] + off[k * 128 + t];
        off[k * 128 + t]++;
        gb[pos] = n;
        out_bins[pos] = (float)n;
        out_mskf[pos] = mb[n] ? 1.0f : 0.0f;
    }
}

// ---------------------------------------------------------------------------
// K4: per-bin pairwise gaussian kernel + fused x_node gather.
// 512 threads. NEW conflict-free staging: warp = (fgroup=w>>2, rblock=w&3);
// lane owns row rb*32+lane, reads its 8 f4 gmem chunks, stores As[f][r] with
// consecutive-r lanes (zero bank conflicts; old layout was 16-way conflicted).
// na accumulated per-fgroup into partials, reduced between two barriers.
// Gram: 136 triangle tiles as 272 8x4 half-tiles on threads 0..271; mirror
// writes; warps 9-15 overlap the x_node gather.
// ---------------------------------------------------------------------------
#define ST 132
__global__ void __launch_bounds__(512, 2)
k_dm(const float4* __restrict__ x_msg4,
     const int* __restrict__ msk,
     const float4* __restrict__ x_node4,
     float* __restrict__ out) {
    const int b   = blockIdx.x / NBINS;
    const int bin = blockIdx.x % NBINS;
    extern __shared__ float sm4[];
    float* As  = sm4;                    // [128][ST], f-major (A transposed)
    float* na  = sm4 + 128 * ST;         // [128]
    float* mm  = na + 128;               // [128]
    float* nap = mm + 128;               // [4][128] na partials
    const int tid  = threadIdx.x;        // 512
    const int w    = tid >> 5;           // 0..15
    const int lane = tid & 31;

    const int* gb = g_bins + ((size_t)b * NBINS + bin) * BS;
    const float4* xb = x_msg4 + (size_t)b * NN * (FM / 4);

    // Conflict-free staging: fgroup fg handles f4 in [fg*8, fg*8+8).
    {
        const int fg = w >> 2;           // 0..3
        const int rb = w & 3;            // 0..3
        const int r  = rb * 32 + lane;   // row owned by this lane
        const int src = gb[r];
        const float m = msk[(size_t)b * NN + src] ? 1.f : 0.f;
        const float4* xrow = xb + (size_t)src * (FM / 4);
        float s = 0.f;
#pragma unroll
        for (int k = 0; k < 8; k++) {
            const int f4 = fg * 8 + k;
            float4 v = xrow[f4];
            v.x *= m; v.y *= m; v.z *= m; v.w *= m;
            As[(4 * f4 + 0) * ST + r] = v.x;
            As[(4 * f4 + 1) * ST + r] = v.y;
            As[(4 * f4 + 2) * ST + r] = v.z;
            As[(4 * f4 + 3) * ST + r] = v.w;
            s += v.x * v.x + v.y * v.y + v.z * v.z + v.w * v.w;
        }
        nap[fg * 128 + r] = s;
        if (fg == 0) mm[r] = m;
    }
    __syncthreads();
    if (tid < 128) {
        na[tid] = (nap[tid] + nap[128 + tid]) + (nap[256 + tid] + nap[384 + tid]);
    }
    __syncthreads();

    if (tid < 272) {
        const int tile = tid >> 1;
        const int half = tid & 1;
        // map tile -> (ty, tx) in upper triangle (tx >= ty) of 16x16 grid
        int ty = 0, rem = tile;
        while (rem >= 16 - ty) { rem -= 16 - ty; ty++; }
        const int tx = ty + rem;
        const int i0 = ty * 8;
        const int j0 = tx * 8 + half * 4;   // 4-col half

        u64 acc2[8][2];
#pragma unroll
        for (int u = 0; u < 8; u++) {
            acc2[u][0] = pack2(0.f, 0.f);
            acc2[u][1] = pack2(0.f, 0.f);
        }

        for (int f = 0; f < FM; f++) {
            const float* row = As + f * ST;
            float4 a0 = *(const float4*)(row + i0);
            float4 a1 = *(const float4*)(row + i0 + 4);
            ulonglong2 q = *(const ulonglong2*)(row + j0);   // (c0,c1),(c2,c3)
            float a[8] = {a0.x, a0.y, a0.z, a0.w, a1.x, a1.y, a1.z, a1.w};
#pragma unroll
            for (int u = 0; u < 8; u++) {
                u64 au = pack2(a[u], a[u]);
                fma2(acc2[u][0], au, q.x);
                fma2(acc2[u][1], au, q.y);
            }
        }

        float* dout = out + OFF_DM + (size_t)blockIdx.x * BS * BS;
        const float c = -0.14426950408889634f;   // -DIST_MULT * log2(e)
        float res[8][4];
#pragma unroll
        for (int u = 0; u < 8; u++) {
            float g[4];
            unpack2(acc2[u][0], g[0], g[1]);
            unpack2(acc2[u][1], g[2], g[3]);
            const float nai = na[i0 + u];
            const float mi  = mm[i0 + u];
#pragma unroll
            for (int v = 0; v < 4; v++) {
                float x = fmaxf(nai + na[j0 + v] - 2.0f * g[v], 1e-6f);
                float d = x * rsqf(x);            // sqrt(x), x >= 1e-6
                float val = ex2f(c * d) * mi * mm[j0 + v];
                res[u][v] = fminf(val, 1.0f);
            }
            *(float4*)(dout + (size_t)(i0 + u) * BS + j0) =
                make_float4(res[u][0], res[u][1], res[u][2], res[u][3]);
        }
        // mirrored 4x8 block at (j0.., i0..) — dm is exactly symmetric
        if (tx != ty) {
#pragma unroll
            for (int v = 0; v < 4; v++) {
                float4* p = (float4*)(dout + (size_t)(j0 + v) * BS + i0);
                p[0] = make_float4(res[0][v], res[1][v], res[2][v], res[3][v]);
                p[1] = make_float4(res[4][v], res[5][v], res[6][v], res[7][v]);
            }
        }
    }

    // Fused x_node gather: 128 rows of 256 floats (64 float4 each).
    // Warps 9-15 reach here right after the na barrier (overlap with gram).
    const float4* xn = x_node4 + (size_t)b * NN * (FN / 4);
    float4* xo = (float4*)(out + OFF_XNODE) + (size_t)blockIdx.x * BS * (FN / 4);
    for (int r = w; r < BS; r += 16) {
        int src = gb[r];
        const float4* s = xn + (size_t)src * (FN / 4);
        float4* d = xo + (size_t)r * (FN / 4);
#pragma unroll
        for (int c4 = 0; c4 < 2; c4++) d[lane + 32 * c4] = s[lane + 32 * c4];
    }
}

// ---------------------------------------------------------------------------
extern "C" void kernel_launch(void* const* d_in, const int* in_sizes, int n_in,
                              void* d_out, int out_size) {
    const float* x_msg  = (const float*)d_in[0];
    const float* x_node = (const float*)d_in[1];
    const int*   msk    = (const int*)d_in[2];
    const float* rot    = (const float*)d_in[3];
    float* out = (float*)d_out;

    const int SM2 = NKEYS * 128 * 2;                         // 51200
    const int SM4 = 128 * ST * 4 + (128 + 128 + 512) * 4;    // 70656
    cudaFuncSetAttribute(k_sort, cudaFuncAttributeMaxDynamicSharedMemorySize, SM2);
    cudaFuncSetAttribute(k_dm,   cudaFuncAttributeMaxDynamicSharedMemorySize, SM4);

    k_proj<<<BB * (NN / 128), 128>>>(x_msg, msk, rot);
    k_sort<<<BB, 128, SM2>>>(msk, out);
    k_dm<<<BB * NBINS, 512, SM4>>>((const float4*)x_msg, msk,
                                   (const float4*)x_node, out);
}